// round 13
// baseline (speedup 1.0000x reference)
#include <cuda_runtime.h>
#include <cuda_fp16.h>
#include <cstdint>

// Problem constants
#define NB    8192
#define DIN   768
#define DLAT  12288
#define KTOP  64
#define CAND_CAP 128
#define CAND_TARGET 72
#define SURV_CAP 768
#define THRESH 2.0f      // fixed pre-filter; adaptive thr72 ~ 2.5 sigma >> 2.0

// ---------------- device scratch (static; no runtime allocs) ----------------
__device__ __half  g_Ah [(size_t)NB   * DIN];    // x in fp16
__device__ __half  g_Bth[(size_t)DLAT * DIN];    // W_enc^T fp16 K-major
__device__ float   g_WT [(size_t)DLAT * DIN];    // W_enc^T fp32
__device__ uint32_t g_surv[(size_t)NB * SURV_CAP]; // packed (key16<<16)|col
__device__ int     g_scount[NB];

// ---------------- helpers ----------------
__device__ __forceinline__ uint32_t smem_u32(const void* p) {
    uint32_t a;
    asm("{ .reg .u64 t; cvta.to.shared.u64 t, %1; cvt.u32.u64 %0, t; }" : "=r"(a) : "l"(p));
    return a;
}
#define CP_ASYNC16(dst, src) \
    asm volatile("cp.async.cg.shared.global [%0], [%1], 16;" :: "r"(dst), "l"(src))
#define CP_COMMIT() asm volatile("cp.async.commit_group;")
#define CP_WAIT(n)  asm volatile("cp.async.wait_group %0;" :: "n"(n))

#define LDMATRIX_X4(r0, r1, r2, r3, addr) \
    asm volatile("ldmatrix.sync.aligned.m8n8.x4.shared.b16 {%0,%1,%2,%3}, [%4];" \
                 : "=r"(r0), "=r"(r1), "=r"(r2), "=r"(r3) : "r"(addr))

#define MMA16816(c0, c1, c2, c3, a0, a1, a2, a3, b0, b1) \
    asm volatile("mma.sync.aligned.m16n8k16.row.col.f32.f16.f16.f32 " \
                 "{%0,%1,%2,%3},{%4,%5,%6,%7},{%8,%9},{%0,%1,%2,%3};" \
                 : "+f"(c0), "+f"(c1), "+f"(c2), "+f"(c3) \
                 : "r"(a0), "r"(a1), "r"(a2), "r"(a3), "r"(b0), "r"(b1))

__device__ __forceinline__ unsigned f2key16(unsigned u) {
    return (u & 0x8000u) ? ((~u) & 0xFFFFu) : (u | 0x8000u);
}

// ---------------------------------------------------------------------------
// Prep kernels
// ---------------------------------------------------------------------------
__global__ void conv_x_kernel(const float* __restrict__ x) {
    int i = blockIdx.x * blockDim.x + threadIdx.x;
    if (i < NB * DIN) g_Ah[i] = __float2half_rn(x[i]);
    if (i < NB) g_scount[i] = 0;       // reset survivor counters every launch
}

// W_enc [DIN][DLAT] -> W^T fp32 + fp16, [DLAT][DIN]
__global__ void conv_wenc_kernel(const float* __restrict__ W) {
    __shared__ float s[32][33];
    const int n0 = blockIdx.x * 32, k0 = blockIdx.y * 32;
    const int tx = threadIdx.x, ty0 = threadIdx.y;     // block 32x8
#pragma unroll
    for (int dy = 0; dy < 32; dy += 8)
        s[ty0 + dy][tx] = W[(size_t)(k0 + ty0 + dy) * DLAT + n0 + tx];
    __syncthreads();
#pragma unroll
    for (int dy = 0; dy < 32; dy += 8) {
        int ty = ty0 + dy;
        float v = s[tx][ty];
        size_t o = (size_t)(n0 + ty) * DIN + k0 + tx;
        g_WT[o]  = v;
        g_Bth[o] = __float2half_rn(v);
    }
}

// ---------------------------------------------------------------------------
// fp16 tensor-core GEMM (mma.sync): H = Ah @ Bth^T (+bias)
// BM=128, BN=128, BK=64 halfs (128B rows, SW128), 3-stage cp.async pipeline.
// Epilogue: NO H store; emits survivors (val >= THRESH) as packed (key,col).
// ---------------------------------------------------------------------------
#define GNIT (DIN / 64)      // 12
#define STG_B 32768          // A 16KB + B 16KB

__global__ __launch_bounds__(256, 2)
void gemm_fp16_kernel(const float* __restrict__ bias) {
    extern __shared__ char sm[];
    const uint32_t sbase = smem_u32(sm);
    const int tid  = threadIdx.x;
    const int lane = tid & 31;
    const int wid  = tid >> 5;
    const int wm   = wid & 1;
    const int wn   = wid >> 1;
    const int bn   = blockIdx.x * 128;
    const int bm   = blockIdx.y * 128;

    float acc[4][4][4];
#pragma unroll
    for (int f = 0; f < 4; f++)
#pragma unroll
        for (int g = 0; g < 4; g++)
#pragma unroll
            for (int q = 0; q < 4; q++) acc[f][g][q] = 0.0f;

    auto load_stage = [&](int it) {
        const int s = it % 3;
        const int koff = it * 64;                    // halfs
        const uint32_t base = sbase + s * STG_B;
#pragma unroll
        for (int q = 0; q < 8; q++) {
            int idx = tid + q * 256;
            int isB = idx >= 1024;
            int id2 = idx - (isB ? 1024 : 0);
            int r  = id2 >> 3;
            int ch = id2 & 7;
            const __half* src = isB
                ? (g_Bth + (size_t)(bn + r) * DIN + koff + ch * 8)
                : (g_Ah  + (size_t)(bm + r) * DIN + koff + ch * 8);
            uint32_t dst = base + (isB ? 16384 : 0) + r * 128 +
                           ((ch ^ (r & 7)) << 4);
            CP_ASYNC16(dst, src);
        }
        CP_COMMIT();
    };

    load_stage(0);
    load_stage(1);

    for (int it = 0; it < GNIT; it++) {
        if (it + 2 < GNIT) CP_WAIT(1); else CP_WAIT(0);
        __syncthreads();
        if (it + 2 < GNIT) load_stage(it + 2);

        const uint32_t sA = sbase + (it % 3) * STG_B;
        const uint32_t sB = sA + 16384;
#pragma unroll
        for (int ks = 0; ks < 4; ks++) {
            uint32_t a[4][4], b[4][2];
#pragma unroll
            for (int f = 0; f < 4; f++) {
                int q  = lane >> 3;
                int r  = wm * 64 + f * 16 + (lane & 7) + ((q & 1) << 3);
                int ch = ks * 2 + (q >> 1);
                uint32_t addr = sA + r * 128 + ((ch ^ (r & 7)) << 4);
                LDMATRIX_X4(a[f][0], a[f][1], a[f][2], a[f][3], addr);
            }
#pragma unroll
            for (int p = 0; p < 2; p++) {
                int q  = lane >> 3;
                int n  = wn * 32 + p * 16 + ((q >> 1) << 3) + (lane & 7);
                int ch = ks * 2 + (q & 1);
                uint32_t addr = sB + n * 128 + ((ch ^ (n & 7)) << 4);
                LDMATRIX_X4(b[2 * p][0], b[2 * p][1], b[2 * p + 1][0], b[2 * p + 1][1], addr);
            }
#pragma unroll
            for (int f = 0; f < 4; f++)
#pragma unroll
                for (int g = 0; g < 4; g++)
                    MMA16816(acc[f][g][0], acc[f][g][1], acc[f][g][2], acc[f][g][3],
                             a[f][0], a[f][1], a[f][2], a[f][3],
                             b[g][0], b[g][1]);
        }
        __syncthreads();
    }

    // epilogue: survivor extraction (val >= THRESH), no H store
#pragma unroll
    for (int f = 0; f < 4; f++) {
#pragma unroll
        for (int g = 0; g < 4; g++) {
            const int r0 = bm + wm * 64 + f * 16 + (lane >> 2);
            const int c0 = bn + wn * 32 + g * 8 + (lane & 3) * 2;
            const float b0 = bias[c0], b1 = bias[c0 + 1];
            float vals[4] = {acc[f][g][0] + b0, acc[f][g][1] + b1,
                             acc[f][g][2] + b0, acc[f][g][3] + b1};
            const int rows[4] = {r0, r0, r0 + 8, r0 + 8};
            const int cols[4] = {c0, c0 + 1, c0, c0 + 1};
#pragma unroll
            for (int v = 0; v < 4; v++) {
                if (vals[v] >= THRESH) {
                    __half h = __float2half_rn(vals[v]);
                    unsigned key = f2key16((unsigned)__half_as_ushort(h));
                    int pos = atomicAdd(&g_scount[rows[v]], 1);
                    if (pos < SURV_CAP)
                        g_surv[(size_t)rows[v] * SURV_CAP + pos] =
                            (key << 16) | (unsigned)cols[v];
                }
            }
        }
    }
}

// ---------------------------------------------------------------------------
// Warp-0 collective: pick highest bucket b with suffix-count >= target.
// ---------------------------------------------------------------------------
__device__ __forceinline__ void select_bucket_warp0(const int* hist, int target, int* out) {
    const int lane = threadIdx.x;   // caller guarantees tid < 32
    int h[8];
    int t = 0;
    const int base = 255 - lane * 8;
#pragma unroll
    for (int j = 0; j < 8; j++) { h[j] = hist[base - j]; t += h[j]; }
    int inc = t;
#pragma unroll
    for (int o = 1; o < 32; o <<= 1) {
        int v = __shfl_up_sync(0xFFFFFFFFu, inc, o);
        if (lane >= o) inc += v;
    }
    const int ex = inc - t;
    int fb = -1, fr = 0, cum = ex;
#pragma unroll
    for (int j = 0; j < 8; j++) {
        cum += h[j];
        if (fb < 0 && cum >= target) { fb = base - j; fr = target - (cum - h[j]); }
    }
    unsigned m = __ballot_sync(0xFFFFFFFFu, fb >= 0);
    if (m == 0) {               // fewer than `target` keys total: select all
        if (lane == 0) { out[0] = 0; out[1] = target; }
        return;
    }
    int src = __ffs(m) - 1;
    int b   = __shfl_sync(0xFFFFFFFFu, fb, src);
    int r   = __shfl_sync(0xFFFFFFFFu, fr, src);
    if (lane == 0) { out[0] = b; out[1] = r; }
}

// ---------------------------------------------------------------------------
// Fused: survivor radix-select (top-72 by fp16 key, tie-inclusive) +
//        exact fp32 rescore (warp-per-candidate) + exact top-64 + z write +
//        sparse decoder (64-row W_dec gather) + recon write.
// ---------------------------------------------------------------------------
__global__ __launch_bounds__(128)
void rescore_decode_kernel(const float* __restrict__ x,
                           const float* __restrict__ b_enc,
                           const float* __restrict__ Wd,
                           const float* __restrict__ bd,
                           float* __restrict__ z,
                           float* __restrict__ recon) {
    __shared__ float    xs[DIN];
    __shared__ uint32_t sv[SURV_CAP];
    __shared__ int      hist[256];
    __shared__ int      sel2[2];
    __shared__ int      ncs;
    __shared__ int      cidx[CAND_CAP];
    __shared__ float    cval[CAND_CAP];
    __shared__ int      slotArr[CAND_CAP];
    __shared__ unsigned char sel[CAND_CAP];
    __shared__ int      sidx[KTOP];
    __shared__ float    sval[KTOP];

    const int tid  = threadIdx.x;
    const int lane = tid & 31;
    const int wid  = tid >> 5;         // 4 warps
    const int row  = blockIdx.x;

    int ns = g_scount[row];
    if (ns > SURV_CAP) ns = SURV_CAP;

    for (int i = tid; i < DIN / 4; i += 128)
        *(float4*)&xs[i * 4] = *(const float4*)&x[(size_t)row * DIN + i * 4];
    for (int i = tid; i < ns; i += 128)
        sv[i] = g_surv[(size_t)row * SURV_CAP + i];
    for (int i = tid; i < 256; i += 128) hist[i] = 0;
    if (tid == 0) ncs = 0;
    __syncthreads();

    // --- adaptive top-72 threshold over survivor fp16 keys (2-pass radix) ---
    for (int i = tid; i < ns; i += 128) atomicAdd(&hist[sv[i] >> 24], 1);
    __syncthreads();
    if (tid < 32) select_bucket_warp0(hist, CAND_TARGET, sel2);
    __syncthreads();
    const int b1 = sel2[0], kRem = sel2[1];
    __syncthreads();
    for (int i = tid; i < 256; i += 128) hist[i] = 0;
    __syncthreads();
    for (int i = tid; i < ns; i += 128) {
        uint32_t k = sv[i] >> 16;
        if ((int)(k >> 8) == b1) atomicAdd(&hist[k & 255], 1);
    }
    __syncthreads();
    if (tid < 32) select_bucket_warp0(hist, kRem, sel2);
    __syncthreads();
    const unsigned thr = ((unsigned)b1 << 8) | (unsigned)sel2[0];

    // --- candidates = {key >= thr}, built in ascending-index order ---
    for (int i = tid; i < ns; i += 128) {
        uint32_t k = sv[i] >> 16;
        if (k >= thr) {
            const int idx = (int)(sv[i] & 0xFFFFu);
            int pos = 0;
            for (int q = 0; q < ns; q++) {
                uint32_t kq = sv[q] >> 16;
                pos += (kq >= thr) && ((int)(sv[q] & 0xFFFFu) < idx);
            }
            if (pos < CAND_CAP) cidx[pos] = idx;
            atomicAdd(&ncs, 1);
        }
    }
    __syncthreads();
    const int nc = (ncs < CAND_CAP) ? ncs : CAND_CAP;

    // --- exact fp32 rescore, one warp per candidate (coalesced) ---
    const float4* x4 = (const float4*)xs;
    for (int t = wid; t < nc; t += 4) {
        const int j = cidx[t];
        const float4* w4 = (const float4*)(g_WT + (size_t)j * DIN);
        float acc = 0.0f;
#pragma unroll
        for (int q = 0; q < 6; q++) {
            const int p = lane + q * 32;
            float4 wv = w4[p];
            float4 xv = x4[p];
            acc = fmaf(wv.x, xv.x, acc);
            acc = fmaf(wv.y, xv.y, acc);
            acc = fmaf(wv.z, xv.z, acc);
            acc = fmaf(wv.w, xv.w, acc);
        }
#pragma unroll
        for (int o = 16; o; o >>= 1)
            acc += __shfl_xor_sync(0xFFFFFFFFu, acc, o);
        if (lane == 0) cval[t] = acc + b_enc[j];
    }
    __syncthreads();

    // --- exact top-64 by (value desc, index asc) ---
    for (int t = tid; t < nc; t += 128) {
        const float v = cval[t];
        const int   j = cidx[t];
        int r = 0;
        for (int q = 0; q < nc; q++) {
            float vq = cval[q];
            r += (vq > v) || (vq == v && cidx[q] < j);
        }
        sel[t] = (r < KTOP) ? 1 : 0;
    }
    __syncthreads();
    if (tid == 0) {
        int s = 0;
        for (int q = 0; q < nc; q++) { slotArr[q] = s; s += sel[q]; }
    }
    __syncthreads();

    // --- z row: zeros then scatter selected; stage (idx,val) ---
    float4* zr4 = (float4*)(z + (size_t)row * DLAT);
    const float4 zf = {0.f, 0.f, 0.f, 0.f};
    for (int i = tid; i < DLAT / 4; i += 128) zr4[i] = zf;
    __syncthreads();
    for (int t = tid; t < nc; t += 128) {
        if (sel[t]) {
            int s = slotArr[t];
            sidx[s] = cidx[t];
            sval[s] = cval[t];
            z[(size_t)row * DLAT + cidx[t]] = cval[t];
        }
    }
    __syncthreads();

    // --- decoder: recon[row,:] = sum_i sval[i] * Wd[sidx[i],:] + bd ---
    float a0 = 0, a1 = 0, a2 = 0, a3 = 0, a4 = 0, a5 = 0;
#pragma unroll 4
    for (int i = 0; i < KTOP; i++) {
        const float* wr = Wd + (size_t)sidx[i] * DIN;
        const float  v  = sval[i];
        a0 = fmaf(v, wr[tid],       a0);
        a1 = fmaf(v, wr[tid + 128], a1);
        a2 = fmaf(v, wr[tid + 256], a2);
        a3 = fmaf(v, wr[tid + 384], a3);
        a4 = fmaf(v, wr[tid + 512], a4);
        a5 = fmaf(v, wr[tid + 640], a5);
    }
    float* rr = recon + (size_t)row * DIN;
    rr[tid]       = a0 + bd[tid];
    rr[tid + 128] = a1 + bd[tid + 128];
    rr[tid + 256] = a2 + bd[tid + 256];
    rr[tid + 384] = a3 + bd[tid + 384];
    rr[tid + 512] = a4 + bd[tid + 512];
    rr[tid + 640] = a5 + bd[tid + 640];
}

// ---------------------------------------------------------------------------
extern "C" void kernel_launch(void* const* d_in, const int* in_sizes, int n_in,
                              void* d_out, int out_size) {
    const float* x     = (const float*)d_in[0];
    const float* W_enc = (const float*)d_in[1];
    const float* b_enc = (const float*)d_in[2];
    const float* W_dec = (const float*)d_in[3];
    const float* b_dec = (const float*)d_in[4];

    float* recon = (float*)d_out;
    float* z     = (float*)d_out + (size_t)NB * DIN;

    conv_x_kernel<<<(NB * DIN + 255) / 256, 256>>>(x);
    conv_wenc_kernel<<<dim3(DLAT / 32, DIN / 32), dim3(32, 8)>>>(W_enc);

    const int gemm_smem = 3 * STG_B;   // 98304
    cudaFuncSetAttribute(gemm_fp16_kernel,
                         cudaFuncAttributeMaxDynamicSharedMemorySize, gemm_smem);
    gemm_fp16_kernel<<<dim3(DLAT / 128, NB / 128), 256, gemm_smem>>>(b_enc);

    rescore_decode_kernel<<<NB, 128>>>(x, b_enc, W_dec, b_dec, z, recon);
}

// round 14
// speedup vs baseline: 1.1065x; 1.1065x over previous
#include <cuda_runtime.h>
#include <cuda_fp16.h>
#include <cstdint>

// Problem constants
#define NB    8192
#define DIN   768
#define DLAT  12288
#define KTOP  64
#define CAND_CAP 128
#define CAND_TARGET 72

// ---------------- device scratch (static; no runtime allocs) ----------------
__device__ __half g_Ah [(size_t)NB   * DIN];    // x in fp16
__device__ __half g_Bth[(size_t)DLAT * DIN];    // W_enc^T fp16 K-major
__device__ float  g_WT [(size_t)DLAT * DIN];    // W_enc^T fp32
__device__ __half g_H  [(size_t)NB   * DLAT];   // h approx fp16
__device__ int    g_cand[(size_t)NB * CAND_CAP];
__device__ int    g_ncand[NB];

// ---------------- helpers ----------------
__device__ __forceinline__ uint32_t smem_u32(const void* p) {
    uint32_t a;
    asm("{ .reg .u64 t; cvta.to.shared.u64 t, %1; cvt.u32.u64 %0, t; }" : "=r"(a) : "l"(p));
    return a;
}
#define CP_ASYNC16(dst, src) \
    asm volatile("cp.async.cg.shared.global [%0], [%1], 16;" :: "r"(dst), "l"(src))
#define CP_COMMIT() asm volatile("cp.async.commit_group;")
#define CP_WAIT(n)  asm volatile("cp.async.wait_group %0;" :: "n"(n))

#define LDMATRIX_X4(r0, r1, r2, r3, addr) \
    asm volatile("ldmatrix.sync.aligned.m8n8.x4.shared.b16 {%0,%1,%2,%3}, [%4];" \
                 : "=r"(r0), "=r"(r1), "=r"(r2), "=r"(r3) : "r"(addr))

#define MMA16816(c0, c1, c2, c3, a0, a1, a2, a3, b0, b1) \
    asm volatile("mma.sync.aligned.m16n8k16.row.col.f32.f16.f16.f32 " \
                 "{%0,%1,%2,%3},{%4,%5,%6,%7},{%8,%9},{%0,%1,%2,%3};" \
                 : "+f"(c0), "+f"(c1), "+f"(c2), "+f"(c3) \
                 : "r"(a0), "r"(a1), "r"(a2), "r"(a3), "r"(b0), "r"(b1))

// ---------------------------------------------------------------------------
// Prep kernels
// ---------------------------------------------------------------------------
__global__ void conv_x_kernel(const float* __restrict__ x) {
    int i = blockIdx.x * blockDim.x + threadIdx.x;
    if (i < NB * DIN) g_Ah[i] = __float2half_rn(x[i]);
}

// W_enc [DIN][DLAT] -> W^T fp32 + fp16, [DLAT][DIN]
__global__ void conv_wenc_kernel(const float* __restrict__ W) {
    __shared__ float s[32][33];
    const int n0 = blockIdx.x * 32, k0 = blockIdx.y * 32;
    const int tx = threadIdx.x, ty0 = threadIdx.y;     // block 32x8
#pragma unroll
    for (int dy = 0; dy < 32; dy += 8)
        s[ty0 + dy][tx] = W[(size_t)(k0 + ty0 + dy) * DLAT + n0 + tx];
    __syncthreads();
#pragma unroll
    for (int dy = 0; dy < 32; dy += 8) {
        int ty = ty0 + dy;
        float v = s[tx][ty];
        size_t o = (size_t)(n0 + ty) * DIN + k0 + tx;
        g_WT[o]  = v;
        g_Bth[o] = __float2half_rn(v);
    }
}

// ---------------------------------------------------------------------------
// fp16 tensor-core GEMM (mma.sync): H = Ah @ Bth^T (+bias), fp16 out
// BM=128, BN=128, BK=64 halfs (128B rows, SW128), 3-stage cp.async pipeline.
// Grid y: first ZF_ROWS rows of blocks are z-fill blocks (DRAM is ~5% busy
// during the GEMM, so the 402MB zero-fill rides along nearly free).
// ---------------------------------------------------------------------------
#define GNIT (DIN / 64)      // 12
#define STG_B 32768          // A 16KB + B 16KB
#define ZF_ROWS 4            // 4*96 = 384 zfill blocks, 1MB each

__global__ __launch_bounds__(256, 2)
void gemm_fp16_kernel(const float* __restrict__ bias, float* __restrict__ z) {
    // ---- z-fill blocks (scheduled first; exit quickly) ----
    if (blockIdx.y < ZF_ROWS) {
        const int blk = blockIdx.y * gridDim.x + blockIdx.x;   // 0..383
        const size_t total4 = (size_t)NB * DLAT / 4;           // 25165824
        const size_t per    = total4 / (ZF_ROWS * 96);         // 65536 float4
        float4* z4 = (float4*)z + (size_t)blk * per;
        const float4 zf = {0.f, 0.f, 0.f, 0.f};
        for (size_t i = threadIdx.x; i < per; i += 256) z4[i] = zf;
        return;
    }

    extern __shared__ char sm[];
    const uint32_t sbase = smem_u32(sm);
    const int tid  = threadIdx.x;
    const int lane = tid & 31;
    const int wid  = tid >> 5;
    const int wm   = wid & 1;
    const int wn   = wid >> 1;
    const int bn   = blockIdx.x * 128;
    const int bm   = (blockIdx.y - ZF_ROWS) * 128;

    float acc[4][4][4];
#pragma unroll
    for (int f = 0; f < 4; f++)
#pragma unroll
        for (int g = 0; g < 4; g++)
#pragma unroll
            for (int q = 0; q < 4; q++) acc[f][g][q] = 0.0f;

    auto load_stage = [&](int it) {
        const int s = it % 3;
        const int koff = it * 64;                    // halfs
        const uint32_t base = sbase + s * STG_B;
#pragma unroll
        for (int q = 0; q < 8; q++) {
            int idx = tid + q * 256;
            int isB = idx >= 1024;
            int id2 = idx - (isB ? 1024 : 0);
            int r  = id2 >> 3;
            int ch = id2 & 7;
            const __half* src = isB
                ? (g_Bth + (size_t)(bn + r) * DIN + koff + ch * 8)
                : (g_Ah  + (size_t)(bm + r) * DIN + koff + ch * 8);
            uint32_t dst = base + (isB ? 16384 : 0) + r * 128 +
                           ((ch ^ (r & 7)) << 4);
            CP_ASYNC16(dst, src);
        }
        CP_COMMIT();
    };

    load_stage(0);
    load_stage(1);

    for (int it = 0; it < GNIT; it++) {
        if (it + 2 < GNIT) CP_WAIT(1); else CP_WAIT(0);
        __syncthreads();
        if (it + 2 < GNIT) load_stage(it + 2);

        const uint32_t sA = sbase + (it % 3) * STG_B;
        const uint32_t sB = sA + 16384;
#pragma unroll
        for (int ks = 0; ks < 4; ks++) {
            uint32_t a[4][4], b[4][2];
#pragma unroll
            for (int f = 0; f < 4; f++) {
                int q  = lane >> 3;
                int r  = wm * 64 + f * 16 + (lane & 7) + ((q & 1) << 3);
                int ch = ks * 2 + (q >> 1);
                uint32_t addr = sA + r * 128 + ((ch ^ (r & 7)) << 4);
                LDMATRIX_X4(a[f][0], a[f][1], a[f][2], a[f][3], addr);
            }
#pragma unroll
            for (int p = 0; p < 2; p++) {
                int q  = lane >> 3;
                int n  = wn * 32 + p * 16 + ((q >> 1) << 3) + (lane & 7);
                int ch = ks * 2 + (q & 1);
                uint32_t addr = sB + n * 128 + ((ch ^ (n & 7)) << 4);
                LDMATRIX_X4(b[2 * p][0], b[2 * p][1], b[2 * p + 1][0], b[2 * p + 1][1], addr);
            }
#pragma unroll
            for (int f = 0; f < 4; f++)
#pragma unroll
                for (int g = 0; g < 4; g++)
                    MMA16816(acc[f][g][0], acc[f][g][1], acc[f][g][2], acc[f][g][3],
                             a[f][0], a[f][1], a[f][2], a[f][3],
                             b[g][0], b[g][1]);
        }
        __syncthreads();
    }

#pragma unroll
    for (int f = 0; f < 4; f++) {
#pragma unroll
        for (int g = 0; g < 4; g++) {
            int r0 = bm + wm * 64 + f * 16 + (lane >> 2);
            int c0 = bn + wn * 32 + g * 8 + (lane & 3) * 2;
            float b0 = bias[c0], b1 = bias[c0 + 1];
            __half2 h0 = __floats2half2_rn(acc[f][g][0] + b0, acc[f][g][1] + b1);
            __half2 h1 = __floats2half2_rn(acc[f][g][2] + b0, acc[f][g][3] + b1);
            *(__half2*)(g_H + (size_t)r0 * DLAT + c0)       = h0;
            *(__half2*)(g_H + (size_t)(r0 + 8) * DLAT + c0) = h1;
        }
    }
}

// ---------------------------------------------------------------------------
// Top-72 candidate selection per row -- 512 threads, 12 packed keys each.
// (R12/R8 champion configuration, verbatim: f2key16 biased keys.)
// ---------------------------------------------------------------------------
__device__ __forceinline__ unsigned f2key16(unsigned u) {
    return (u & 0x8000u) ? ((~u) & 0xFFFFu) : (u | 0x8000u);
}

__device__ __forceinline__ void select_bucket_warp0(const int* hist, int target, int* out) {
    const int lane = threadIdx.x;   // caller guarantees tid < 32
    int h[8];
    int t = 0;
    const int base = 255 - lane * 8;
#pragma unroll
    for (int j = 0; j < 8; j++) { h[j] = hist[base - j]; t += h[j]; }
    int inc = t;
#pragma unroll
    for (int o = 1; o < 32; o <<= 1) {
        int v = __shfl_up_sync(0xFFFFFFFFu, inc, o);
        if (lane >= o) inc += v;
    }
    const int ex = inc - t;
    int fb = -1, fr = 0, cum = ex;
#pragma unroll
    for (int j = 0; j < 8; j++) {
        cum += h[j];
        if (fb < 0 && cum >= target) { fb = base - j; fr = target - (cum - h[j]); }
    }
    unsigned m = __ballot_sync(0xFFFFFFFFu, fb >= 0);
    int src = __ffs(m) - 1;
    int b   = __shfl_sync(0xFFFFFFFFu, fb, src);
    int r   = __shfl_sync(0xFFFFFFFFu, fr, src);
    if (lane == 0) { out[0] = b; out[1] = r; }
}

__global__ __launch_bounds__(512)
void topk16_kernel() {
    __shared__ int hist[256];
    __shared__ int sel_s[2];
    __shared__ int wsum[16];
    __shared__ int wbase[16];

    const int tid  = threadIdx.x;
    const int lane = tid & 31;
    const int wrp  = tid >> 5;
    const int row  = blockIdx.x;
    const uint4* hrow = (const uint4*)(g_H + (size_t)row * DLAT);

    uint32_t kp[12];
#pragma unroll
    for (int q = 0; q < 3; q++) {
        uint4 v = hrow[tid + q * 512];
        uint32_t w[4] = {v.x, v.y, v.z, v.w};
#pragma unroll
        for (int p = 0; p < 4; p++) {
            uint32_t lo = f2key16(w[p] & 0xFFFFu);
            uint32_t hi = f2key16(w[p] >> 16);
            kp[q * 4 + p] = lo | (hi << 16);
        }
    }
    if (tid < 256) hist[tid] = 0;
    __syncthreads();

#pragma unroll
    for (int j = 0; j < 12; j++) {
        atomicAdd(&hist[(kp[j] >> 8) & 0xFFu], 1);
        atomicAdd(&hist[kp[j] >> 24], 1);
    }
    __syncthreads();
    if (tid < 32) select_bucket_warp0(hist, CAND_TARGET, sel_s);
    __syncthreads();
    const int b1   = sel_s[0];
    const int kRem = sel_s[1];
    __syncthreads();

    if (tid < 256) hist[tid] = 0;
    __syncthreads();
#pragma unroll
    for (int j = 0; j < 12; j++) {
        uint32_t k0 = kp[j] & 0xFFFFu, k1 = kp[j] >> 16;
        if ((int)(k0 >> 8) == b1) atomicAdd(&hist[k0 & 255], 1);
        if ((int)(k1 >> 8) == b1) atomicAdd(&hist[k1 & 255], 1);
    }
    __syncthreads();
    if (tid < 32) select_bucket_warp0(hist, kRem, sel_s);
    __syncthreads();
    const unsigned thr = ((unsigned)b1 << 8) | (unsigned)sel_s[0];

    int c = 0;
#pragma unroll
    for (int j = 0; j < 12; j++) {
        c += ((kp[j] & 0xFFFFu) >= thr);
        c += ((kp[j] >> 16) >= thr);
    }
    int inc = c;
#pragma unroll
    for (int o = 1; o < 32; o <<= 1) {
        int v = __shfl_up_sync(0xFFFFFFFFu, inc, o);
        if (lane >= o) inc += v;
    }
    if (lane == 31) wsum[wrp] = inc;
    __syncthreads();
    if (tid == 0) {
        int s = 0;
        for (int w = 0; w < 16; w++) { wbase[w] = s; s += wsum[w]; }
        g_ncand[row] = (s < CAND_CAP) ? s : CAND_CAP;
    }
    __syncthreads();
    int base = wbase[wrp] + inc - c;

    int l = 0;
#pragma unroll
    for (int j = 0; j < 12; j++) {
        const int idx0 = (tid + (j >> 2) * 512) * 8 + (j & 3) * 2;
        uint32_t k0 = kp[j] & 0xFFFFu, k1 = kp[j] >> 16;
        if (k0 >= thr) {
            int s = base + l; l++;
            if (s < CAND_CAP) g_cand[(size_t)row * CAND_CAP + s] = idx0;
        }
        if (k1 >= thr) {
            int s = base + l; l++;
            if (s < CAND_CAP) g_cand[(size_t)row * CAND_CAP + s] = idx0 + 1;
        }
    }
}

// ---------------------------------------------------------------------------
// Fused: exact fp32 rescore (warp-per-candidate) + exact top-64 + z scatter
//        + sparse decoder (64-row W_dec gather) + recon write.
// z rows pre-zeroed by the GEMM launch's zfill blocks.
// ---------------------------------------------------------------------------
__global__ __launch_bounds__(128)
void rescore_decode_kernel(const float* __restrict__ x,
                           const float* __restrict__ b_enc,
                           const float* __restrict__ Wd,
                           const float* __restrict__ bd,
                           float* __restrict__ z,
                           float* __restrict__ recon) {
    __shared__ float xs[DIN];
    __shared__ int   cidx[CAND_CAP];
    __shared__ float cval[CAND_CAP];
    __shared__ int   slotArr[CAND_CAP];
    __shared__ unsigned char sel[CAND_CAP];
    __shared__ int   sidx[KTOP];
    __shared__ float sval[KTOP];

    const int tid  = threadIdx.x;
    const int lane = tid & 31;
    const int wid  = tid >> 5;         // 4 warps
    const int row  = blockIdx.x;
    const int nc   = g_ncand[row];

    for (int i = tid; i < DIN / 4; i += 128)
        *(float4*)&xs[i * 4] = *(const float4*)&x[(size_t)row * DIN + i * 4];
    for (int i = tid; i < nc; i += 128)
        cidx[i] = g_cand[(size_t)row * CAND_CAP + i];
    __syncthreads();

    const float4* x4 = (const float4*)xs;
    for (int t = wid; t < nc; t += 4) {
        const int j = cidx[t];
        const float4* w4 = (const float4*)(g_WT + (size_t)j * DIN);
        float acc = 0.0f;
#pragma unroll
        for (int q = 0; q < 6; q++) {
            const int p = lane + q * 32;
            float4 wv = w4[p];
            float4 xv = x4[p];
            acc = fmaf(wv.x, xv.x, acc);
            acc = fmaf(wv.y, xv.y, acc);
            acc = fmaf(wv.z, xv.z, acc);
            acc = fmaf(wv.w, xv.w, acc);
        }
#pragma unroll
        for (int o = 16; o; o >>= 1)
            acc += __shfl_xor_sync(0xFFFFFFFFu, acc, o);
        if (lane == 0) cval[t] = acc + b_enc[j];
    }
    __syncthreads();

    for (int t = tid; t < nc; t += 128) {
        const float v = cval[t];
        const int   j = cidx[t];
        int r = 0;
        for (int q = 0; q < nc; q++) {
            float vq = cval[q];
            r += (vq > v) || (vq == v && cidx[q] < j);
        }
        sel[t] = (r < KTOP) ? 1 : 0;
    }
    __syncthreads();
    if (tid == 0) {
        int s = 0;
        for (int q = 0; q < nc; q++) { slotArr[q] = s; s += sel[q]; }
    }
    __syncthreads();

    // z row pre-zeroed: scatter selected only
    for (int t = tid; t < nc; t += 128) {
        if (sel[t]) {
            int s = slotArr[t];
            sidx[s] = cidx[t];
            sval[s] = cval[t];
            z[(size_t)row * DLAT + cidx[t]] = cval[t];
        }
    }
    __syncthreads();

    float a0 = 0, a1 = 0, a2 = 0, a3 = 0, a4 = 0, a5 = 0;
#pragma unroll 4
    for (int i = 0; i < KTOP; i++) {
        const float* wr = Wd + (size_t)sidx[i] * DIN;
        const float  v  = sval[i];
        a0 = fmaf(v, wr[tid],       a0);
        a1 = fmaf(v, wr[tid + 128], a1);
        a2 = fmaf(v, wr[tid + 256], a2);
        a3 = fmaf(v, wr[tid + 384], a3);
        a4 = fmaf(v, wr[tid + 512], a4);
        a5 = fmaf(v, wr[tid + 640], a5);
    }
    float* rr = recon + (size_t)row * DIN;
    rr[tid]       = a0 + bd[tid];
    rr[tid + 128] = a1 + bd[tid + 128];
    rr[tid + 256] = a2 + bd[tid + 256];
    rr[tid + 384] = a3 + bd[tid + 384];
    rr[tid + 512] = a4 + bd[tid + 512];
    rr[tid + 640] = a5 + bd[tid + 640];
}

// ---------------------------------------------------------------------------
extern "C" void kernel_launch(void* const* d_in, const int* in_sizes, int n_in,
                              void* d_out, int out_size) {
    const float* x     = (const float*)d_in[0];
    const float* W_enc = (const float*)d_in[1];
    const float* b_enc = (const float*)d_in[2];
    const float* W_dec = (const float*)d_in[3];
    const float* b_dec = (const float*)d_in[4];

    float* recon = (float*)d_out;
    float* z     = (float*)d_out + (size_t)NB * DIN;

    conv_x_kernel<<<(NB * DIN + 255) / 256, 256>>>(x);
    conv_wenc_kernel<<<dim3(DLAT / 32, DIN / 32), dim3(32, 8)>>>(W_enc);

    const int gemm_smem = 3 * STG_B;   // 98304
    cudaFuncSetAttribute(gemm_fp16_kernel,
                         cudaFuncAttributeMaxDynamicSharedMemorySize, gemm_smem);
    gemm_fp16_kernel<<<dim3(DLAT / 128, NB / 128 + ZF_ROWS), 256, gemm_smem>>>(b_enc, z);

    topk16_kernel<<<NB, 512>>>();

    rescore_decode_kernel<<<NB, 128>>>(x, b_enc, W_dec, b_dec, z, recon);
}